// round 16
// baseline (speedup 1.0000x reference)
#include <cuda_runtime.h>
#include <cuda_fp16.h>
#include <mma.h>

using namespace nvcuda;

#define DD 64
#define MAXN 50000
#define MAXE 800000
#define ETILES 4          // edge tiles per block (weight reuse)

// ---------------- scratch (device globals: no allocation allowed) ----------
__device__ __align__(16) __half g_esrc[(size_t)MAXN * DD];   // fp16 gather arrays
__device__ __align__(16) __half g_edst[(size_t)MAXN * DD];
__device__ __align__(16) __half g_Bh  [(size_t)MAXN * DD];
__device__ __align__(16) float g_xs  [(size_t)MAXN * DD];
__device__ __align__(16) float g_xpre[(size_t)MAXN * DD];
// packed aggregation: per (node, group): [num0..3 fp16 | den0..3 fp16] = 16B
__device__ __align__(16) __half g_nd [(size_t)MAXN * 128];
__device__ __align__(16) __half g_m  [(size_t)MAXE * DD];    // fp16 m storage
// [0:64) edge_sum [64:128) edge_sumsq [128:192) node_sum [192:256) node_sumsq
__device__ __align__(16) float g_stats[256];

__device__ __forceinline__ float sigmoidf_(float x) {
    return __fdividef(1.0f, 1.0f + __expf(-x));
}
__device__ __forceinline__ void red4(float* p, float a, float b, float c, float d) {
    asm volatile("{\n\t.reg .u64 q;\n\tcvta.to.global.u64 q, %0;\n\t"
                 "red.global.add.v4.f32 [q], {%1, %2, %3, %4};\n\t}"
                 :: "l"(p), "f"(a), "f"(b), "f"(c), "f"(d) : "memory");
}
// 8 fp16 adds in one L2 op (sm_90+): {num01, num23, den01, den23}
__device__ __forceinline__ void red4h(__half* p, unsigned a, unsigned b,
                                      unsigned c, unsigned d) {
    asm volatile("{\n\t.reg .u64 q;\n\tcvta.to.global.u64 q, %0;\n\t"
                 "red.global.add.noftz.v4.f16x2 [q], {%1, %2, %3, %4};\n\t}"
                 :: "l"(p), "r"(a), "r"(b), "r"(c), "r"(d) : "memory");
}

#define LDA 72
#define LDM 68

// ---------------- node-side 4 GEMMs via fp16 wmma (R12 core, unchanged) -----
__global__ __launch_bounds__(256) void node_gemm4_mma(
    const float* __restrict__ nf,
    const float* __restrict__ Wsg, const float* __restrict__ bsg,
    const float* __restrict__ Wdg, const float* __restrict__ bdg,
    const float* __restrict__ Wsu, const float* __restrict__ bsu,
    const float* __restrict__ Wdu, const float* __restrict__ bdu,
    int n)
{
    __shared__ __align__(16) __half shA  [64 * LDA];
    __shared__ __align__(16) __half shBhi[64 * LDA];
    __shared__ __align__(16) float shC  [64 * LDM];

    const int tid = threadIdx.x;
    const int wid = tid >> 5;
    const int tile0 = blockIdx.x * 64;

    for (int i = tid; i < 64 * 16; i += 256) {
        int r = i >> 4, c4 = (i & 15) << 2;
        float4 v = make_float4(0.f, 0.f, 0.f, 0.f);
        int row = tile0 + r;
        if (row < n) v = *reinterpret_cast<const float4*>(nf + (size_t)row * DD + c4);
        int base = r * LDA + c4;
        *reinterpret_cast<__half2*>(&shA[base])     = __floats2half2_rn(v.x, v.y);
        *reinterpret_cast<__half2*>(&shA[base + 2]) = __floats2half2_rn(v.z, v.w);
    }

    const float* Ws[4] = {Wsg, Wdg, Wsu, Wdu};
    const float* bs[4] = {bsg, bdg, bsu, bdu};
    __half* outs16[4] = {g_esrc, g_edst, (__half*)0, g_Bh};

    const int mrow = (wid >> 1) * 16;
    const int ncol = (wid & 1) * 32;
    const int cg = tid & 15, rg = tid >> 4;

    #pragma unroll
    for (int p = 0; p < 4; ++p) {
        __syncthreads();
        for (int i = tid; i < 64 * 16; i += 256) {
            int k = i >> 4, c4 = (i & 15) << 2;
            float4 w = *reinterpret_cast<const float4*>(Ws[p] + k * DD + c4);
            int base = k * LDA + c4;
            *reinterpret_cast<__half2*>(&shBhi[base])     = __floats2half2_rn(w.x, w.y);
            *reinterpret_cast<__half2*>(&shBhi[base + 2]) = __floats2half2_rn(w.z, w.w);
        }
        __syncthreads();

        wmma::fragment<wmma::accumulator, 16, 16, 16, float> c0, c1;
        wmma::fill_fragment(c0, 0.0f);
        wmma::fill_fragment(c1, 0.0f);
        #pragma unroll
        for (int k = 0; k < 4; k++) {
            wmma::fragment<wmma::matrix_a, 16, 16, 16, __half, wmma::row_major> ah;
            wmma::fragment<wmma::matrix_b, 16, 16, 16, __half, wmma::row_major> bh0, bh1;
            wmma::load_matrix_sync(ah, &shA[mrow * LDA + k * 16], LDA);
            wmma::load_matrix_sync(bh0, &shBhi[(k * 16) * LDA + ncol], LDA);
            wmma::load_matrix_sync(bh1, &shBhi[(k * 16) * LDA + ncol + 16], LDA);
            wmma::mma_sync(c0, ah, bh0, c0);
            wmma::mma_sync(c1, ah, bh1, c1);
        }
        wmma::store_matrix_sync(&shC[mrow * LDM + ncol],      c0, LDM, wmma::mem_row_major);
        wmma::store_matrix_sync(&shC[mrow * LDM + ncol + 16], c1, LDM, wmma::mem_row_major);
        __syncthreads();

        float4 bb = reinterpret_cast<const float4*>(bs[p])[cg];
        #pragma unroll
        for (int r = 0; r < 4; r++) {
            int row = tile0 + rg * 4 + r;
            if (row >= n) continue;
            float4 cv = *reinterpret_cast<const float4*>(&shC[(rg * 4 + r) * LDM + (cg << 2)]);
            cv.x += bb.x; cv.y += bb.y; cv.z += bb.z; cv.w += bb.w;
            if (p == 2) {
                *reinterpret_cast<float4*>(g_xs + (size_t)row * DD + (cg << 2)) = cv;
            } else {
                union { __half2 h2[2]; uint2 u; } pk;
                pk.h2[0] = __floats2half2_rn(cv.x, cv.y);
                pk.h2[1] = __floats2half2_rn(cv.z, cv.w);
                *reinterpret_cast<uint2*>(outs16[p] + (size_t)row * DD + (cg << 2)) = pk.u;
            }
        }
    }

    // zero packed num|den aggregation array for this tile + stats (block 0)
    uint4 z4 = make_uint4(0u, 0u, 0u, 0u);
    for (int i = tid; i < 64 * 16; i += 256) {
        int r = i >> 4, g = i & 15;
        int row = tile0 + r;
        if (row < n)
            *reinterpret_cast<uint4*>(g_nd + (size_t)row * 128 + g * 8) = z4;
    }
    if (blockIdx.x == 0 && tid < 256) g_stats[tid] = 0.f;
}

// ---------------- edge pass: ETILES x 64 edges/block, B loaded once ---------
// smem: abuf (A fp16 9216B, shM f32 17408B overlay) + separate B (9216B kept).
__global__ __launch_bounds__(256) void edge_pass1_mma(
    const float* __restrict__ ef, const int* __restrict__ eidx,
    const float* __restrict__ Weg, const float* __restrict__ beg,
    int nE)
{
    __shared__ __align__(16) char abuf[64 * LDM * 4];      // 17408 B: A | shM overlay
    __shared__ __align__(16) __half shBhi[64 * LDA];       // 9216 B, persists
    __shared__ int shS[64], shD[64];
    __shared__ float shSum[64], shSq[64];

    __half* shAhi = reinterpret_cast<__half*>(abuf);
    float*  shM   = reinterpret_cast<float*>(abuf);

    const int tid = threadIdx.x;
    const int wid = tid >> 5;
    const int cg = tid & 15, rg = tid >> 4;
    const int mrow = (wid >> 1) * 16;
    const int ncol = (wid & 1) * 32;

    if (tid < 64) { shSum[tid] = 0.f; shSq[tid] = 0.f; }

    // B: W[k][n] row-major -> fp16  (loaded ONCE, reused across ETILES)
    for (int i = tid; i < 64 * 16; i += 256) {
        int k = i >> 4, c4 = (i & 15) << 2;
        float4 w = *reinterpret_cast<const float4*>(Weg + k * DD + c4);
        int base = k * LDA + c4;
        *reinterpret_cast<__half2*>(&shBhi[base])     = __floats2half2_rn(w.x, w.y);
        *reinterpret_cast<__half2*>(&shBhi[base + 2]) = __floats2half2_rn(w.z, w.w);
    }

    float4 bb = reinterpret_cast<const float4*>(beg)[cg];
    float lsum[4] = {0.f, 0.f, 0.f, 0.f};
    float lsq[4]  = {0.f, 0.f, 0.f, 0.f};

    for (int t = 0; t < ETILES; t++) {
        const int tile0 = (blockIdx.x * ETILES + t) * 64;
        if (tile0 >= nE) break;

        __syncthreads();   // prior epilogue's shM reads done before A overwrite
        if (tid < 64) {
            int e = tile0 + tid;
            shS[tid] = (e < nE) ? eidx[e] : 0;
            shD[tid] = (e < nE) ? eidx[(size_t)nE + e] : 0;
        }
        for (int i = tid; i < 64 * 16; i += 256) {
            int r = i >> 4, c4 = (i & 15) << 2;
            float4 v = make_float4(0.f, 0.f, 0.f, 0.f);
            int e = tile0 + r;
            if (e < nE) v = *reinterpret_cast<const float4*>(ef + (size_t)e * DD + c4);
            int base = r * LDA + c4;
            *reinterpret_cast<__half2*>(&shAhi[base])     = __floats2half2_rn(v.x, v.y);
            *reinterpret_cast<__half2*>(&shAhi[base + 2]) = __floats2half2_rn(v.z, v.w);
        }
        __syncthreads();

        wmma::fragment<wmma::accumulator, 16, 16, 16, float> c0, c1;
        wmma::fill_fragment(c0, 0.0f);
        wmma::fill_fragment(c1, 0.0f);
        #pragma unroll
        for (int k = 0; k < 4; k++) {
            wmma::fragment<wmma::matrix_a, 16, 16, 16, __half, wmma::row_major> ah;
            wmma::fragment<wmma::matrix_b, 16, 16, 16, __half, wmma::row_major> bh0, bh1;
            wmma::load_matrix_sync(ah, &shAhi[mrow * LDA + k * 16], LDA);
            wmma::load_matrix_sync(bh0, &shBhi[(k * 16) * LDA + ncol], LDA);
            wmma::load_matrix_sync(bh1, &shBhi[(k * 16) * LDA + ncol + 16], LDA);
            wmma::mma_sync(c0, ah, bh0, c0);
            wmma::mma_sync(c1, ah, bh1, c1);
        }
        __syncthreads();   // A reads done before shM overlay store
        wmma::store_matrix_sync(&shM[mrow * LDM + ncol],      c0, LDM, wmma::mem_row_major);
        wmma::store_matrix_sync(&shM[mrow * LDM + ncol + 16], c1, LDM, wmma::mem_row_major);
        __syncthreads();

        // ---------- epilogue: fp16 gathers, fp16 m store, red4h scatter -----
        #pragma unroll
        for (int r = 0; r < 4; r++) {
            int li = rg * 4 + r;
            int e = tile0 + li;
            if (e >= nE) continue;
            int s = shS[li], d = shD[li];
            float4 mm = *reinterpret_cast<const float4*>(&shM[li * LDM + (cg << 2)]);
            uint2 eu = *reinterpret_cast<const uint2*>(g_esrc + (size_t)s * DD + (cg << 2));
            uint2 du = *reinterpret_cast<const uint2*>(g_edst + (size_t)d * DD + (cg << 2));
            uint2 bu = *reinterpret_cast<const uint2*>(g_Bh   + (size_t)s * DD + (cg << 2));
            float2 es01 = __half22float2(*reinterpret_cast<__half2*>(&eu.x));
            float2 es23 = __half22float2(*reinterpret_cast<__half2*>(&eu.y));
            float2 ed01 = __half22float2(*reinterpret_cast<__half2*>(&du.x));
            float2 ed23 = __half22float2(*reinterpret_cast<__half2*>(&du.y));
            float2 bh01 = __half22float2(*reinterpret_cast<__half2*>(&bu.x));
            float2 bh23 = __half22float2(*reinterpret_cast<__half2*>(&bu.y));
            float m0 = mm.x + bb.x + es01.x + ed01.x;
            float m1 = mm.y + bb.y + es01.y + ed01.y;
            float m2 = mm.z + bb.z + es23.x + ed23.x;
            float m3 = mm.w + bb.w + es23.y + ed23.y;
            union { __half2 h2[2]; uint2 u; } pk;
            pk.h2[0] = __floats2half2_rn(m0, m1);
            pk.h2[1] = __floats2half2_rn(m2, m3);
            *reinterpret_cast<uint2*>(g_m + (size_t)e * DD + (cg << 2)) = pk.u;
            float s0 = sigmoidf_(m0), s1 = sigmoidf_(m1);
            float s2 = sigmoidf_(m2), s3 = sigmoidf_(m3);
            union { __half2 h; unsigned u; } n01, n23, d01, d23;
            n01.h = __floats2half2_rn(bh01.x * s0, bh01.y * s1);
            n23.h = __floats2half2_rn(bh23.x * s2, bh23.y * s3);
            d01.h = __floats2half2_rn(s0, s1);
            d23.h = __floats2half2_rn(s2, s3);
            red4h(g_nd + (size_t)d * 128 + cg * 8, n01.u, n23.u, d01.u, d23.u);
            lsum[0] += m0; lsum[1] += m1; lsum[2] += m2; lsum[3] += m3;
            lsq[0] += m0 * m0; lsq[1] += m1 * m1; lsq[2] += m2 * m2; lsq[3] += m3 * m3;
        }
    }

    // ---------- stats reduction (once per block) -----------------------------
    #pragma unroll
    for (int j = 0; j < 4; j++) {
        lsum[j] += __shfl_xor_sync(0xffffffffu, lsum[j], 16);
        lsq[j]  += __shfl_xor_sync(0xffffffffu, lsq[j], 16);
    }
    if ((tid & 16) == 0) {
        #pragma unroll
        for (int j = 0; j < 4; j++) {
            atomicAdd(&shSum[(cg << 2) + j], lsum[j]);
            atomicAdd(&shSq [(cg << 2) + j], lsq[j]);
        }
    }
    __syncthreads();
    if (tid < 16) {
        int t4 = tid << 2;
        red4(&g_stats[t4], shSum[t4], shSum[t4 + 1], shSum[t4 + 2], shSum[t4 + 3]);
    } else if (tid < 32) {
        int t4 = (tid - 16) << 2;
        red4(&g_stats[64 + t4], shSq[t4], shSq[t4 + 1], shSq[t4 + 2], shSq[t4 + 3]);
    }
}

// ---------------- node pre-activation: packed fp16 nd read (unchanged) ------
__global__ __launch_bounds__(256) void node_pre(int nN)
{
    __shared__ float shSum[64], shSq[64];
    if (threadIdx.x < 64) { shSum[threadIdx.x] = 0.f; shSq[threadIdx.x] = 0.f; }
    __syncthreads();

    const int stride = gridDim.x * 256;
    const int tot = nN * 16;
    const int cg = threadIdx.x & 15;
    float l0 = 0.f, l1 = 0.f, l2 = 0.f, l3 = 0.f;
    float q0 = 0.f, q1 = 0.f, q2 = 0.f, q3 = 0.f;
    for (int idx = blockIdx.x * 256 + threadIdx.x; idx < tot; idx += stride) {
        float4 xs = reinterpret_cast<const float4*>(g_xs)[idx];
        uint4 nd = *reinterpret_cast<const uint4*>(g_nd + (size_t)idx * 8);
        float2 nu01 = __half22float2(*reinterpret_cast<__half2*>(&nd.x));
        float2 nu23 = __half22float2(*reinterpret_cast<__half2*>(&nd.y));
        float2 de01 = __half22float2(*reinterpret_cast<__half2*>(&nd.z));
        float2 de23 = __half22float2(*reinterpret_cast<__half2*>(&nd.w));
        float4 v;
        v.x = xs.x + nu01.x / (de01.x + 1e-6f);
        v.y = xs.y + nu01.y / (de01.y + 1e-6f);
        v.z = xs.z + nu23.x / (de23.x + 1e-6f);
        v.w = xs.w + nu23.y / (de23.y + 1e-6f);
        reinterpret_cast<float4*>(g_xpre)[idx] = v;
        l0 += v.x; l1 += v.y; l2 += v.z; l3 += v.w;
        q0 += v.x * v.x; q1 += v.y * v.y; q2 += v.z * v.z; q3 += v.w * v.w;
    }
    l0 += __shfl_xor_sync(0xffffffffu, l0, 16); q0 += __shfl_xor_sync(0xffffffffu, q0, 16);
    l1 += __shfl_xor_sync(0xffffffffu, l1, 16); q1 += __shfl_xor_sync(0xffffffffu, q1, 16);
    l2 += __shfl_xor_sync(0xffffffffu, l2, 16); q2 += __shfl_xor_sync(0xffffffffu, q2, 16);
    l3 += __shfl_xor_sync(0xffffffffu, l3, 16); q3 += __shfl_xor_sync(0xffffffffu, q3, 16);
    if ((threadIdx.x & 16) == 0) {
        atomicAdd(&shSum[(cg << 2) + 0], l0); atomicAdd(&shSum[(cg << 2) + 1], l1);
        atomicAdd(&shSum[(cg << 2) + 2], l2); atomicAdd(&shSum[(cg << 2) + 3], l3);
        atomicAdd(&shSq [(cg << 2) + 0], q0); atomicAdd(&shSq [(cg << 2) + 1], q1);
        atomicAdd(&shSq [(cg << 2) + 2], q2); atomicAdd(&shSq [(cg << 2) + 3], q3);
    }
    __syncthreads();
    if (threadIdx.x < 16) {
        int t4 = threadIdx.x << 2;
        red4(&g_stats[128 + t4], shSum[t4], shSum[t4 + 1], shSum[t4 + 2], shSum[t4 + 3]);
    } else if (threadIdx.x < 32) {
        int t4 = (threadIdx.x - 16) << 2;
        red4(&g_stats[192 + t4], shSq[t4], shSq[t4 + 1], shSq[t4 + 2], shSq[t4 + 3]);
    }
}

// ---------------- merged outputs + fused BN finalize (fp16 m read) ----------
__global__ __launch_bounds__(256) void outputs_k(
    const float* __restrict__ nf, const float* __restrict__ ef,
    const float* __restrict__ gn, const float* __restrict__ btn,
    const float* __restrict__ ge, const float* __restrict__ bte,
    float* __restrict__ outx, float* __restrict__ outy,
    int nN, int nE)
{
    __shared__ float sEsc[64], sEsh[64], sNsc[64], sNsh[64];
    int t = threadIdx.x;
    if (t < 64) {
        float invE = 1.f / (float)nE;
        float me = g_stats[t] * invE;
        float ve = g_stats[64 + t] * invE - me * me;
        float sce = rsqrtf(ve + 1e-5f) * ge[t];
        sEsc[t] = sce; sEsh[t] = bte[t] - me * sce;
    } else if (t < 128) {
        int u = t - 64;
        float invN = 1.f / (float)nN;
        float mn = g_stats[128 + u] * invN;
        float vn = g_stats[192 + u] * invN - mn * mn;
        float scn = rsqrtf(vn + 1e-5f) * gn[u];
        sNsc[u] = scn; sNsh[u] = btn[u] - mn * scn;
    }
    __syncthreads();

    int idx = blockIdx.x * 256 + threadIdx.x;
    int nTot = nN * 16;
    if (idx < nTot) {
        int cg = idx & 15;
        float4 sc = *reinterpret_cast<const float4*>(&sNsc[cg << 2]);
        float4 sh = *reinterpret_cast<const float4*>(&sNsh[cg << 2]);
        float4 xp = reinterpret_cast<const float4*>(g_xpre)[idx];
        float4 nv = reinterpret_cast<const float4*>(nf)[idx];
        float t0 = xp.x * sc.x + sh.x;
        float t1 = xp.y * sc.y + sh.y;
        float t2 = xp.z * sc.z + sh.z;
        float t3 = xp.w * sc.w + sh.w;
        float4 o;
        o.x = nv.x + t0 * sigmoidf_(t0);
        o.y = nv.y + t1 * sigmoidf_(t1);
        o.z = nv.z + t2 * sigmoidf_(t2);
        o.w = nv.w + t3 * sigmoidf_(t3);
        reinterpret_cast<float4*>(outx)[idx] = o;
    } else {
        int j = idx - nTot;
        if (j >= nE * 16) return;
        int cg = j & 15;
        float4 sc = *reinterpret_cast<const float4*>(&sEsc[cg << 2]);
        float4 sh = *reinterpret_cast<const float4*>(&sEsh[cg << 2]);
        uint2 mu = *reinterpret_cast<const uint2*>(g_m + (size_t)j * 4);
        float2 f01 = __half22float2(*reinterpret_cast<__half2*>(&mu.x));
        float2 f23 = __half22float2(*reinterpret_cast<__half2*>(&mu.y));
        float4 ev = reinterpret_cast<const float4*>(ef)[j];
        float t0 = f01.x * sc.x + sh.x;
        float t1 = f01.y * sc.y + sh.y;
        float t2 = f23.x * sc.z + sh.z;
        float t3 = f23.y * sc.w + sh.w;
        float4 o;
        o.x = ev.x + t0 * sigmoidf_(t0);
        o.y = ev.y + t1 * sigmoidf_(t1);
        o.z = ev.z + t2 * sigmoidf_(t2);
        o.w = ev.w + t3 * sigmoidf_(t3);
        reinterpret_cast<float4*>(outy)[j] = o;
    }
}

// ---------------- launch -----------------------------------------------------
extern "C" void kernel_launch(void* const* d_in, const int* in_sizes, int n_in,
                              void* d_out, int out_size)
{
    (void)n_in; (void)out_size;
    const int* eidx  = (const int*)d_in[0];   // edge_index is int32 (JAX x64 disabled)
    const float* nf  = (const float*)d_in[1];
    const float* ef  = (const float*)d_in[2];
    const float* Wsg = (const float*)d_in[3];  const float* bsg = (const float*)d_in[4];
    const float* Wdg = (const float*)d_in[5];  const float* bdg = (const float*)d_in[6];
    const float* Weg = (const float*)d_in[7];  const float* beg = (const float*)d_in[8];
    const float* Wsu = (const float*)d_in[9];  const float* bsu = (const float*)d_in[10];
    const float* Wdu = (const float*)d_in[11]; const float* bdu = (const float*)d_in[12];
    const float* gmn = (const float*)d_in[13]; const float* btn = (const float*)d_in[14];
    const float* gme = (const float*)d_in[15]; const float* bte = (const float*)d_in[16];

    int nE = in_sizes[0] / 2;
    int nN = in_sizes[1] / DD;

    float* outx = (float*)d_out;
    float* outy = outx + (size_t)nN * DD;

    node_gemm4_mma<<<(nN + 63) / 64, 256>>>(nf, Wsg, bsg, Wdg, bdg, Wsu, bsu, Wdu, bdu, nN);
    edge_pass1_mma<<<(nE + 64 * ETILES - 1) / (64 * ETILES), 256>>>(ef, eidx, Weg, beg, nE);
    node_pre<<<391, 256>>>(nN);
    outputs_k<<<((nN + nE) * 16 + 255) / 256, 256>>>(nf, ef, gmn, btn, gme, bte,
                                                     outx, outy, nN, nE);
}

// round 17
// speedup vs baseline: 1.0908x; 1.0908x over previous
#include <cuda_runtime.h>
#include <cuda_fp16.h>
#include <mma.h>

using namespace nvcuda;

#define DD 64
#define MAXN 50000
#define MAXE 800000

// ---------------- scratch (device globals: no allocation allowed) ----------
__device__ __align__(16) __half g_esrc[(size_t)MAXN * DD];   // fp16 gather arrays
__device__ __align__(16) __half g_edst[(size_t)MAXN * DD];
__device__ __align__(16) __half g_Bh  [(size_t)MAXN * DD];
__device__ __align__(16) __half g_xs  [(size_t)MAXN * DD];   // fp16 streams
__device__ __align__(16) __half g_xpre[(size_t)MAXN * DD];
// packed aggregation: per (node, group): [num0..3 fp16 | den0..3 fp16] = 16B
__device__ __align__(16) __half g_nd [(size_t)MAXN * 128];
__device__ __align__(16) __half g_m  [(size_t)MAXE * DD];    // fp16 m storage
// [0:64) edge_sum [64:128) edge_sumsq [128:192) node_sum [192:256) node_sumsq
__device__ __align__(16) float g_stats[256];

__device__ __forceinline__ float sigmoidf_(float x) {
    return __fdividef(1.0f, 1.0f + __expf(-x));
}
__device__ __forceinline__ void red4(float* p, float a, float b, float c, float d) {
    asm volatile("{\n\t.reg .u64 q;\n\tcvta.to.global.u64 q, %0;\n\t"
                 "red.global.add.v4.f32 [q], {%1, %2, %3, %4};\n\t}"
                 :: "l"(p), "f"(a), "f"(b), "f"(c), "f"(d) : "memory");
}
// 8 fp16 adds in one L2 op (sm_90+): {num01, num23, den01, den23}
__device__ __forceinline__ void red4h(__half* p, unsigned a, unsigned b,
                                      unsigned c, unsigned d) {
    asm volatile("{\n\t.reg .u64 q;\n\tcvta.to.global.u64 q, %0;\n\t"
                 "red.global.add.noftz.v4.f16x2 [q], {%1, %2, %3, %4};\n\t}"
                 :: "l"(p), "r"(a), "r"(b), "r"(c), "r"(d) : "memory");
}

#define LDA 72
#define LDM 68

// ---------------- node-side 4 GEMMs via fp16 wmma (all outputs fp16) --------
__global__ __launch_bounds__(256) void node_gemm4_mma(
    const float* __restrict__ nf,
    const float* __restrict__ Wsg, const float* __restrict__ bsg,
    const float* __restrict__ Wdg, const float* __restrict__ bdg,
    const float* __restrict__ Wsu, const float* __restrict__ bsu,
    const float* __restrict__ Wdu, const float* __restrict__ bdu,
    int n)
{
    __shared__ __align__(16) __half shA  [64 * LDA];
    __shared__ __align__(16) __half shBhi[64 * LDA];
    __shared__ __align__(16) float shC  [64 * LDM];

    const int tid = threadIdx.x;
    const int wid = tid >> 5;
    const int tile0 = blockIdx.x * 64;

    for (int i = tid; i < 64 * 16; i += 256) {
        int r = i >> 4, c4 = (i & 15) << 2;
        float4 v = make_float4(0.f, 0.f, 0.f, 0.f);
        int row = tile0 + r;
        if (row < n) v = *reinterpret_cast<const float4*>(nf + (size_t)row * DD + c4);
        int base = r * LDA + c4;
        *reinterpret_cast<__half2*>(&shA[base])     = __floats2half2_rn(v.x, v.y);
        *reinterpret_cast<__half2*>(&shA[base + 2]) = __floats2half2_rn(v.z, v.w);
    }

    const float* Ws[4] = {Wsg, Wdg, Wsu, Wdu};
    const float* bs[4] = {bsg, bdg, bsu, bdu};
    __half* outs16[4] = {g_esrc, g_edst, g_xs, g_Bh};

    const int mrow = (wid >> 1) * 16;
    const int ncol = (wid & 1) * 32;
    const int cg = tid & 15, rg = tid >> 4;

    #pragma unroll
    for (int p = 0; p < 4; ++p) {
        __syncthreads();
        for (int i = tid; i < 64 * 16; i += 256) {
            int k = i >> 4, c4 = (i & 15) << 2;
            float4 w = *reinterpret_cast<const float4*>(Ws[p] + k * DD + c4);
            int base = k * LDA + c4;
            *reinterpret_cast<__half2*>(&shBhi[base])     = __floats2half2_rn(w.x, w.y);
            *reinterpret_cast<__half2*>(&shBhi[base + 2]) = __floats2half2_rn(w.z, w.w);
        }
        __syncthreads();

        wmma::fragment<wmma::accumulator, 16, 16, 16, float> c0, c1;
        wmma::fill_fragment(c0, 0.0f);
        wmma::fill_fragment(c1, 0.0f);
        #pragma unroll
        for (int k = 0; k < 4; k++) {
            wmma::fragment<wmma::matrix_a, 16, 16, 16, __half, wmma::row_major> ah;
            wmma::fragment<wmma::matrix_b, 16, 16, 16, __half, wmma::row_major> bh0, bh1;
            wmma::load_matrix_sync(ah, &shA[mrow * LDA + k * 16], LDA);
            wmma::load_matrix_sync(bh0, &shBhi[(k * 16) * LDA + ncol], LDA);
            wmma::load_matrix_sync(bh1, &shBhi[(k * 16) * LDA + ncol + 16], LDA);
            wmma::mma_sync(c0, ah, bh0, c0);
            wmma::mma_sync(c1, ah, bh1, c1);
        }
        wmma::store_matrix_sync(&shC[mrow * LDM + ncol],      c0, LDM, wmma::mem_row_major);
        wmma::store_matrix_sync(&shC[mrow * LDM + ncol + 16], c1, LDM, wmma::mem_row_major);
        __syncthreads();

        float4 bb = reinterpret_cast<const float4*>(bs[p])[cg];
        #pragma unroll
        for (int r = 0; r < 4; r++) {
            int row = tile0 + rg * 4 + r;
            if (row >= n) continue;
            float4 cv = *reinterpret_cast<const float4*>(&shC[(rg * 4 + r) * LDM + (cg << 2)]);
            cv.x += bb.x; cv.y += bb.y; cv.z += bb.z; cv.w += bb.w;
            union { __half2 h2[2]; uint2 u; } pk;
            pk.h2[0] = __floats2half2_rn(cv.x, cv.y);
            pk.h2[1] = __floats2half2_rn(cv.z, cv.w);
            *reinterpret_cast<uint2*>(outs16[p] + (size_t)row * DD + (cg << 2)) = pk.u;
        }
    }

    // zero packed num|den aggregation array for this tile + stats (block 0)
    uint4 z4 = make_uint4(0u, 0u, 0u, 0u);
    for (int i = tid; i < 64 * 16; i += 256) {
        int r = i >> 4, g = i & 15;
        int row = tile0 + r;
        if (row < n)
            *reinterpret_cast<uint4*>(g_nd + (size_t)row * 128 + g * 8) = z4;
    }
    if (blockIdx.x == 0 && tid < 256) g_stats[tid] = 0.f;
}

// ---------------- edge pass: R15 (64 edges/block) ---------------------------
__global__ __launch_bounds__(256) void edge_pass1_mma(
    const float* __restrict__ ef, const int* __restrict__ eidx,
    const float* __restrict__ Weg, const float* __restrict__ beg,
    int nE)
{
    __shared__ __align__(16) char buf[64 * LDA * 2 * 2];   // Ahi | Bhi (18432 B)
    __shared__ int shS[64], shD[64];
    __shared__ float shSum[64], shSq[64];

    __half* shAhi = reinterpret_cast<__half*>(buf);
    __half* shBhi = reinterpret_cast<__half*>(buf + 64 * LDA * 2);
    float*  shM   = reinterpret_cast<float*>(buf);          // 64x68 f32 overlay

    const int tid = threadIdx.x;
    const int wid = tid >> 5;
    const int tile0 = blockIdx.x * 64;

    if (tid < 64) {
        shSum[tid] = 0.f; shSq[tid] = 0.f;
        int e = tile0 + tid;
        shS[tid] = (e < nE) ? eidx[e] : 0;
        shD[tid] = (e < nE) ? eidx[(size_t)nE + e] : 0;
    }

    // A: edge_feats rows -> fp16
    for (int i = tid; i < 64 * 16; i += 256) {
        int r = i >> 4, c4 = (i & 15) << 2;
        float4 v = make_float4(0.f, 0.f, 0.f, 0.f);
        int e = tile0 + r;
        if (e < nE) v = *reinterpret_cast<const float4*>(ef + (size_t)e * DD + c4);
        int base = r * LDA + c4;
        *reinterpret_cast<__half2*>(&shAhi[base])     = __floats2half2_rn(v.x, v.y);
        *reinterpret_cast<__half2*>(&shAhi[base + 2]) = __floats2half2_rn(v.z, v.w);
    }
    // B: W[k][n] row-major -> fp16
    for (int i = tid; i < 64 * 16; i += 256) {
        int k = i >> 4, c4 = (i & 15) << 2;
        float4 w = *reinterpret_cast<const float4*>(Weg + k * DD + c4);
        int base = k * LDA + c4;
        *reinterpret_cast<__half2*>(&shBhi[base])     = __floats2half2_rn(w.x, w.y);
        *reinterpret_cast<__half2*>(&shBhi[base + 2]) = __floats2half2_rn(w.z, w.w);
    }
    __syncthreads();

    // GEMM: single-term fp16, fp32 accumulate
    const int mrow = (wid >> 1) * 16;
    const int ncol = (wid & 1) * 32;
    wmma::fragment<wmma::accumulator, 16, 16, 16, float> c0, c1;
    wmma::fill_fragment(c0, 0.0f);
    wmma::fill_fragment(c1, 0.0f);
    #pragma unroll
    for (int k = 0; k < 4; k++) {
        wmma::fragment<wmma::matrix_a, 16, 16, 16, __half, wmma::row_major> ah;
        wmma::fragment<wmma::matrix_b, 16, 16, 16, __half, wmma::row_major> bh0, bh1;
        wmma::load_matrix_sync(ah, &shAhi[mrow * LDA + k * 16], LDA);
        wmma::load_matrix_sync(bh0, &shBhi[(k * 16) * LDA + ncol], LDA);
        wmma::load_matrix_sync(bh1, &shBhi[(k * 16) * LDA + ncol + 16], LDA);
        wmma::mma_sync(c0, ah, bh0, c0);
        wmma::mma_sync(c1, ah, bh1, c1);
    }
    __syncthreads();
    wmma::store_matrix_sync(&shM[mrow * LDM + ncol],      c0, LDM, wmma::mem_row_major);
    wmma::store_matrix_sync(&shM[mrow * LDM + ncol + 16], c1, LDM, wmma::mem_row_major);
    __syncthreads();

    // ---------- epilogue: fp16 gathers, fp16 m store, red4h scatter ---------
    const int cg = tid & 15, rg = tid >> 4;
    float4 bb = reinterpret_cast<const float4*>(beg)[cg];
    float lsum[4] = {0.f, 0.f, 0.f, 0.f};
    float lsq[4]  = {0.f, 0.f, 0.f, 0.f};
    #pragma unroll
    for (int r = 0; r < 4; r++) {
        int li = rg * 4 + r;
        int e = tile0 + li;
        if (e >= nE) continue;
        int s = shS[li], d = shD[li];
        float4 mm = *reinterpret_cast<const float4*>(&shM[li * LDM + (cg << 2)]);
        uint2 eu = *reinterpret_cast<const uint2*>(g_esrc + (size_t)s * DD + (cg << 2));
        uint2 du = *reinterpret_cast<const uint2*>(g_edst + (size_t)d * DD + (cg << 2));
        uint2 bu = *reinterpret_cast<const uint2*>(g_Bh   + (size_t)s * DD + (cg << 2));
        float2 es01 = __half22float2(*reinterpret_cast<__half2*>(&eu.x));
        float2 es23 = __half22float2(*reinterpret_cast<__half2*>(&eu.y));
        float2 ed01 = __half22float2(*reinterpret_cast<__half2*>(&du.x));
        float2 ed23 = __half22float2(*reinterpret_cast<__half2*>(&du.y));
        float2 bh01 = __half22float2(*reinterpret_cast<__half2*>(&bu.x));
        float2 bh23 = __half22float2(*reinterpret_cast<__half2*>(&bu.y));
        float m0 = mm.x + bb.x + es01.x + ed01.x;
        float m1 = mm.y + bb.y + es01.y + ed01.y;
        float m2 = mm.z + bb.z + es23.x + ed23.x;
        float m3 = mm.w + bb.w + es23.y + ed23.y;
        union { __half2 h2[2]; uint2 u; } pk;
        pk.h2[0] = __floats2half2_rn(m0, m1);
        pk.h2[1] = __floats2half2_rn(m2, m3);
        *reinterpret_cast<uint2*>(g_m + (size_t)e * DD + (cg << 2)) = pk.u;
        float s0 = sigmoidf_(m0), s1 = sigmoidf_(m1);
        float s2 = sigmoidf_(m2), s3 = sigmoidf_(m3);
        union { __half2 h; unsigned u; } n01, n23, d01, d23;
        n01.h = __floats2half2_rn(bh01.x * s0, bh01.y * s1);
        n23.h = __floats2half2_rn(bh23.x * s2, bh23.y * s3);
        d01.h = __floats2half2_rn(s0, s1);
        d23.h = __floats2half2_rn(s2, s3);
        red4h(g_nd + (size_t)d * 128 + cg * 8, n01.u, n23.u, d01.u, d23.u);
        lsum[0] += m0; lsum[1] += m1; lsum[2] += m2; lsum[3] += m3;
        lsq[0] += m0 * m0; lsq[1] += m1 * m1; lsq[2] += m2 * m2; lsq[3] += m3 * m3;
    }

    #pragma unroll
    for (int j = 0; j < 4; j++) {
        lsum[j] += __shfl_xor_sync(0xffffffffu, lsum[j], 16);
        lsq[j]  += __shfl_xor_sync(0xffffffffu, lsq[j], 16);
    }
    if ((tid & 16) == 0) {
        #pragma unroll
        for (int j = 0; j < 4; j++) {
            atomicAdd(&shSum[(cg << 2) + j], lsum[j]);
            atomicAdd(&shSq [(cg << 2) + j], lsq[j]);
        }
    }
    __syncthreads();
    if (tid < 16) {
        int t4 = tid << 2;
        red4(&g_stats[t4], shSum[t4], shSum[t4 + 1], shSum[t4 + 2], shSum[t4 + 3]);
    } else if (tid < 32) {
        int t4 = (tid - 16) << 2;
        red4(&g_stats[64 + t4], shSq[t4], shSq[t4 + 1], shSq[t4 + 2], shSq[t4 + 3]);
    }
}

// ---------------- node pre-activation: fp16 xs/nd in, fp16 xpre out ---------
__global__ __launch_bounds__(256) void node_pre(int nN)
{
    __shared__ float shSum[64], shSq[64];
    if (threadIdx.x < 64) { shSum[threadIdx.x] = 0.f; shSq[threadIdx.x] = 0.f; }
    __syncthreads();

    const int stride = gridDim.x * 256;
    const int tot = nN * 16;
    const int cg = threadIdx.x & 15;
    float l0 = 0.f, l1 = 0.f, l2 = 0.f, l3 = 0.f;
    float q0 = 0.f, q1 = 0.f, q2 = 0.f, q3 = 0.f;
    for (int idx = blockIdx.x * 256 + threadIdx.x; idx < tot; idx += stride) {
        uint2 xu = *reinterpret_cast<const uint2*>(g_xs + (size_t)idx * 4);
        float2 xs01 = __half22float2(*reinterpret_cast<__half2*>(&xu.x));
        float2 xs23 = __half22float2(*reinterpret_cast<__half2*>(&xu.y));
        uint4 nd = *reinterpret_cast<const uint4*>(g_nd + (size_t)idx * 8);
        float2 nu01 = __half22float2(*reinterpret_cast<__half2*>(&nd.x));
        float2 nu23 = __half22float2(*reinterpret_cast<__half2*>(&nd.y));
        float2 de01 = __half22float2(*reinterpret_cast<__half2*>(&nd.z));
        float2 de23 = __half22float2(*reinterpret_cast<__half2*>(&nd.w));
        float4 v;
        v.x = xs01.x + nu01.x / (de01.x + 1e-6f);
        v.y = xs01.y + nu01.y / (de01.y + 1e-6f);
        v.z = xs23.x + nu23.x / (de23.x + 1e-6f);
        v.w = xs23.y + nu23.y / (de23.y + 1e-6f);
        union { __half2 h2[2]; uint2 u; } pk;
        pk.h2[0] = __floats2half2_rn(v.x, v.y);
        pk.h2[1] = __floats2half2_rn(v.z, v.w);
        *reinterpret_cast<uint2*>(g_xpre + (size_t)idx * 4) = pk.u;
        l0 += v.x; l1 += v.y; l2 += v.z; l3 += v.w;
        q0 += v.x * v.x; q1 += v.y * v.y; q2 += v.z * v.z; q3 += v.w * v.w;
    }
    l0 += __shfl_xor_sync(0xffffffffu, l0, 16); q0 += __shfl_xor_sync(0xffffffffu, q0, 16);
    l1 += __shfl_xor_sync(0xffffffffu, l1, 16); q1 += __shfl_xor_sync(0xffffffffu, q1, 16);
    l2 += __shfl_xor_sync(0xffffffffu, l2, 16); q2 += __shfl_xor_sync(0xffffffffu, q2, 16);
    l3 += __shfl_xor_sync(0xffffffffu, l3, 16); q3 += __shfl_xor_sync(0xffffffffu, q3, 16);
    if ((threadIdx.x & 16) == 0) {
        atomicAdd(&shSum[(cg << 2) + 0], l0); atomicAdd(&shSum[(cg << 2) + 1], l1);
        atomicAdd(&shSum[(cg << 2) + 2], l2); atomicAdd(&shSum[(cg << 2) + 3], l3);
        atomicAdd(&shSq [(cg << 2) + 0], q0); atomicAdd(&shSq [(cg << 2) + 1], q1);
        atomicAdd(&shSq [(cg << 2) + 2], q2); atomicAdd(&shSq [(cg << 2) + 3], q3);
    }
    __syncthreads();
    if (threadIdx.x < 16) {
        int t4 = threadIdx.x << 2;
        red4(&g_stats[128 + t4], shSum[t4], shSum[t4 + 1], shSum[t4 + 2], shSum[t4 + 3]);
    } else if (threadIdx.x < 32) {
        int t4 = (threadIdx.x - 16) << 2;
        red4(&g_stats[192 + t4], shSq[t4], shSq[t4 + 1], shSq[t4 + 2], shSq[t4 + 3]);
    }
}

// ---------------- merged outputs + fused BN finalize (fp16 m/xpre reads) ----
__global__ __launch_bounds__(256) void outputs_k(
    const float* __restrict__ nf, const float* __restrict__ ef,
    const float* __restrict__ gn, const float* __restrict__ btn,
    const float* __restrict__ ge, const float* __restrict__ bte,
    float* __restrict__ outx, float* __restrict__ outy,
    int nN, int nE)
{
    __shared__ float sEsc[64], sEsh[64], sNsc[64], sNsh[64];
    int t = threadIdx.x;
    if (t < 64) {
        float invE = 1.f / (float)nE;
        float me = g_stats[t] * invE;
        float ve = g_stats[64 + t] * invE - me * me;
        float sce = rsqrtf(ve + 1e-5f) * ge[t];
        sEsc[t] = sce; sEsh[t] = bte[t] - me * sce;
    } else if (t < 128) {
        int u = t - 64;
        float invN = 1.f / (float)nN;
        float mn = g_stats[128 + u] * invN;
        float vn = g_stats[192 + u] * invN - mn * mn;
        float scn = rsqrtf(vn + 1e-5f) * gn[u];
        sNsc[u] = scn; sNsh[u] = btn[u] - mn * scn;
    }
    __syncthreads();

    int idx = blockIdx.x * 256 + threadIdx.x;
    int nTot = nN * 16;
    if (idx < nTot) {
        int cg = idx & 15;
        float4 sc = *reinterpret_cast<const float4*>(&sNsc[cg << 2]);
        float4 sh = *reinterpret_cast<const float4*>(&sNsh[cg << 2]);
        uint2 xu = *reinterpret_cast<const uint2*>(g_xpre + (size_t)idx * 4);
        float2 xp01 = __half22float2(*reinterpret_cast<__half2*>(&xu.x));
        float2 xp23 = __half22float2(*reinterpret_cast<__half2*>(&xu.y));
        float4 nv = reinterpret_cast<const float4*>(nf)[idx];
        float t0 = xp01.x * sc.x + sh.x;
        float t1 = xp01.y * sc.y + sh.y;
        float t2 = xp23.x * sc.z + sh.z;
        float t3 = xp23.y * sc.w + sh.w;
        float4 o;
        o.x = nv.x + t0 * sigmoidf_(t0);
        o.y = nv.y + t1 * sigmoidf_(t1);
        o.z = nv.z + t2 * sigmoidf_(t2);
        o.w = nv.w + t3 * sigmoidf_(t3);
        reinterpret_cast<float4*>(outx)[idx] = o;
    } else {
        int j = idx - nTot;
        if (j >= nE * 16) return;
        int cg = j & 15;
        float4 sc = *reinterpret_cast<const float4*>(&sEsc[cg << 2]);
        float4 sh = *reinterpret_cast<const float4*>(&sEsh[cg << 2]);
        uint2 mu = *reinterpret_cast<const uint2*>(g_m + (size_t)j * 4);
        float2 f01 = __half22float2(*reinterpret_cast<__half2*>(&mu.x));
        float2 f23 = __half22float2(*reinterpret_cast<__half2*>(&mu.y));
        float4 ev = reinterpret_cast<const float4*>(ef)[j];
        float t0 = f01.x * sc.x + sh.x;
        float t1 = f01.y * sc.y + sh.y;
        float t2 = f23.x * sc.z + sh.z;
        float t3 = f23.y * sc.w + sh.w;
        float4 o;
        o.x = ev.x + t0 * sigmoidf_(t0);
        o.y = ev.y + t1 * sigmoidf_(t1);
        o.z = ev.z + t2 * sigmoidf_(t2);
        o.w = ev.w + t3 * sigmoidf_(t3);
        reinterpret_cast<float4*>(outy)[j] = o;
    }
}

// ---------------- launch -----------------------------------------------------
extern "C" void kernel_launch(void* const* d_in, const int* in_sizes, int n_in,
                              void* d_out, int out_size)
{
    (void)n_in; (void)out_size;
    const int* eidx  = (const int*)d_in[0];   // edge_index is int32 (JAX x64 disabled)
    const float* nf  = (const float*)d_in[1];
    const float* ef  = (const float*)d_in[2];
    const float* Wsg = (const float*)d_in[3];  const float* bsg = (const float*)d_in[4];
    const float* Wdg = (const float*)d_in[5];  const float* bdg = (const float*)d_in[6];
    const float* Weg = (const float*)d_in[7];  const float* beg = (const float*)d_in[8];
    const float* Wsu = (const float*)d_in[9];  const float* bsu = (const float*)d_in[10];
    const float* Wdu = (const float*)d_in[11]; const float* bdu = (const float*)d_in[12];
    const float* gmn = (const float*)d_in[13]; const float* btn = (const float*)d_in[14];
    const float* gme = (const float*)d_in[15]; const float* bte = (const float*)d_in[16];

    int nE = in_sizes[0] / 2;
    int nN = in_sizes[1] / DD;

    float* outx = (float*)d_out;
    float* outy = outx + (size_t)nN * DD;

    node_gemm4_mma<<<(nN + 63) / 64, 256>>>(nf, Wsg, bsg, Wdg, bdg, Wsu, bsu, Wdu, bdu, nN);
    edge_pass1_mma<<<(nE + 63) / 64, 256>>>(ef, eidx, Weg, beg, nE);
    node_pre<<<391, 256>>>(nN);
    outputs_k<<<((nN + nE) * 16 + 255) / 256, 256>>>(nf, ef, gmn, btn, gme, bte,
                                                     outx, outy, nN, nE);
}